// round 1
// baseline (speedup 1.0000x reference)
#include <cuda_runtime.h>
#include <cfloat>

// Problem constants
#define BATCH     32
#define NSPATIAL  4096
#define CDIM      512
#define EDIM      128

// Tiling
#define TM        128                 // rows per CTA tile
#define BK        16                  // K slice
#define NCHUNK    (NSPATIAL / TM)     // 32 chunks per batch
#define NT        (CDIM / BK)         // 32 K-tiles
#define AS_STRIDE (TM + 4)            // padded A-tile stride (floats)

// Scratch: per (batch, chunk, e): top3 + min3 candidates (6 floats) -> 3 MB
__device__ float g_cand[BATCH * NCHUNK * EDIM * 6];

// ---- packed fp32x2 helpers (Blackwell) ----
__device__ __forceinline__ void fma2(unsigned long long& d,
                                     unsigned long long a,
                                     unsigned long long b) {
    asm("fma.rn.f32x2 %0, %1, %2, %0;" : "+l"(d) : "l"(a), "l"(b));
}
__device__ __forceinline__ unsigned long long dup2(float a) {
    unsigned long long r;
    asm("mov.b64 %0, {%1, %1};" : "=l"(r) : "f"(a));
    return r;
}

// ---- sorted top-3 / min-3 insertion ----
__device__ __forceinline__ void ins_top(float v, float& t0, float& t1, float& t2) {
    if (v > t2) {
        if (v > t1) {
            t2 = t1;
            if (v > t0) { t1 = t0; t0 = v; } else { t1 = v; }
        } else {
            t2 = v;
        }
    }
}
__device__ __forceinline__ void ins_min(float v, float& m0, float& m1, float& m2) {
    if (v < m2) {
        if (v < m1) {
            m2 = m1;
            if (v < m0) { m1 = m0; m0 = v; } else { m1 = v; }
        } else {
            m2 = v;
        }
    }
}

// Kernel 1: fused GEMM (128x128x512 tile) + per-column top3/min3 candidates.
// grid = (NCHUNK, BATCH), block = 256 threads, dynamic smem = 64 KB.
__global__ __launch_bounds__(256, 2)
void weldon_gemm_pool_kernel(const float* __restrict__ x,
                             const float* __restrict__ W) {
    extern __shared__ float smem[];
    // As: [2][BK][AS_STRIDE] (transposed: [k][m]), Bs: [2][BK][EDIM]
    float* As = smem;                              // 2*16*132 = 4224 floats
    float* Bs = smem + 2 * BK * AS_STRIDE;         // 2*16*128 = 4096 floats
    float* Fs = smem;                              // reused after GEMM: [128][128]

    const int tid = threadIdx.x;
    const int tx = tid & 15;        // column group (8 cols)
    const int ty = tid >> 4;        // row group (8 rows)
    const int chunk = blockIdx.x;
    const int b = blockIdx.y;

    const float* xg = x + ((size_t)b * NSPATIAL + (size_t)chunk * TM) * CDIM;

    unsigned long long acc[8][4];
#pragma unroll
    for (int i = 0; i < 8; ++i)
#pragma unroll
        for (int j = 0; j < 4; ++j) acc[i][j] = 0ull;

    // ---- preload tile 0 into buffer 0 ----
#pragma unroll
    for (int u = 0; u < 2; ++u) {
        int v = tid + u * 256;                 // float4 index in [0,512)
        // A: row = v>>2, k-quad = v&3
        int ar = v >> 2, ak = (v & 3) * 4;
        float4 av = *(const float4*)(xg + (size_t)ar * CDIM + ak);
        As[(ak + 0) * AS_STRIDE + ar] = av.x;
        As[(ak + 1) * AS_STRIDE + ar] = av.y;
        As[(ak + 2) * AS_STRIDE + ar] = av.z;
        As[(ak + 3) * AS_STRIDE + ar] = av.w;
        // B: k-row = v>>5, col = (v&31)*4
        int br = v >> 5, bc = (v & 31) * 4;
        float4 bv = *(const float4*)(W + (size_t)br * EDIM + bc);
        *(float4*)&Bs[br * EDIM + bc] = bv;
    }
    __syncthreads();

    int buf = 0;
    float4 a_reg[2], b_reg[2];

    for (int t = 0; t < NT; ++t) {
        const bool has_next = (t + 1 < NT);
        const int k0n = (t + 1) * BK;
        if (has_next) {
#pragma unroll
            for (int u = 0; u < 2; ++u) {
                int v = tid + u * 256;
                a_reg[u] = *(const float4*)(xg + (size_t)(v >> 2) * CDIM + k0n + (v & 3) * 4);
                b_reg[u] = *(const float4*)(W + (size_t)(k0n + (v >> 5)) * EDIM + (v & 31) * 4);
            }
        }

        const float* Asb = As + buf * BK * AS_STRIDE;
        const float* Bsb = Bs + buf * BK * EDIM;
#pragma unroll
        for (int kk = 0; kk < BK; ++kk) {
            float4 a0 = *(const float4*)&Asb[kk * AS_STRIDE + ty * 8];
            float4 a1 = *(const float4*)&Asb[kk * AS_STRIDE + ty * 8 + 4];
            unsigned long long bv[4];
#pragma unroll
            for (int j = 0; j < 4; ++j)
                bv[j] = *(const unsigned long long*)&Bsb[kk * EDIM + tx * 8 + j * 2];
            float av8[8] = {a0.x, a0.y, a0.z, a0.w, a1.x, a1.y, a1.z, a1.w};
#pragma unroll
            for (int i = 0; i < 8; ++i) {
                unsigned long long a2 = dup2(av8[i]);
#pragma unroll
                for (int j = 0; j < 4; ++j) fma2(acc[i][j], a2, bv[j]);
            }
        }

        if (has_next) {
            int nb = buf ^ 1;
            float* Asn = As + nb * BK * AS_STRIDE;
            float* Bsn = Bs + nb * BK * EDIM;
#pragma unroll
            for (int u = 0; u < 2; ++u) {
                int v = tid + u * 256;
                int ar = v >> 2, ak = (v & 3) * 4;
                Asn[(ak + 0) * AS_STRIDE + ar] = a_reg[u].x;
                Asn[(ak + 1) * AS_STRIDE + ar] = a_reg[u].y;
                Asn[(ak + 2) * AS_STRIDE + ar] = a_reg[u].z;
                Asn[(ak + 3) * AS_STRIDE + ar] = a_reg[u].w;
                int br = v >> 5, bc = (v & 31) * 4;
                *(float4*)&Bsn[br * EDIM + bc] = b_reg[u];
            }
        }
        __syncthreads();
        buf ^= 1;
    }

    // ---- epilogue: spill tile to smem (reuse), per-column top3/min3 ----
#pragma unroll
    for (int i = 0; i < 8; ++i) {
        int row = ty * 8 + i;
#pragma unroll
        for (int j = 0; j < 4; ++j)
            *(unsigned long long*)&Fs[row * EDIM + tx * 8 + j * 2] = acc[i][j];
    }
    __syncthreads();

    if (tid < EDIM) {
        float t0 = -FLT_MAX, t1 = -FLT_MAX, t2 = -FLT_MAX;
        float m0 = FLT_MAX, m1 = FLT_MAX, m2 = FLT_MAX;
#pragma unroll 4
        for (int r = 0; r < TM; ++r) {
            float v = Fs[r * EDIM + tid];
            ins_top(v, t0, t1, t2);
            ins_min(v, m0, m1, m2);
        }
        float* dst = g_cand + ((size_t)(b * NCHUNK + chunk) * EDIM + tid) * 6;
        dst[0] = t0; dst[1] = t1; dst[2] = t2;
        dst[3] = m0; dst[4] = m1; dst[5] = m2;
    }
}

// Kernel 2: merge chunk candidates, pool, L2-normalize per batch.
// grid = BATCH, block = EDIM (128)
__global__ void weldon_reduce_kernel(float* __restrict__ out) {
    const int b = blockIdx.x;
    const int e = threadIdx.x;

    float t0 = -FLT_MAX, t1 = -FLT_MAX, t2 = -FLT_MAX;
    float m0 = FLT_MAX, m1 = FLT_MAX, m2 = FLT_MAX;
    const float* base = g_cand + (size_t)b * NCHUNK * EDIM * 6 + (size_t)e * 6;
#pragma unroll 4
    for (int c = 0; c < NCHUNK; ++c) {
        const float* p = base + (size_t)c * EDIM * 6;
        ins_top(p[0], t0, t1, t2);
        ins_top(p[1], t0, t1, t2);
        ins_top(p[2], t0, t1, t2);
        ins_min(p[3], m0, m1, m2);
        ins_min(p[4], m0, m1, m2);
        ins_min(p[5], m0, m1, m2);
    }
    float ps = (t0 + t1 + t2) + (m0 + m1 + m2);

    // block-wide sum of squares (128 threads = 4 warps)
    float sq = ps * ps;
#pragma unroll
    for (int off = 16; off > 0; off >>= 1)
        sq += __shfl_xor_sync(0xffffffffu, sq, off);
    __shared__ float wsum[4];
    if ((e & 31) == 0) wsum[e >> 5] = sq;
    __syncthreads();
    float tot = wsum[0] + wsum[1] + wsum[2] + wsum[3];

    out[b * EDIM + e] = ps * rsqrtf(fmaxf(tot, 1e-12f));
}

extern "C" void kernel_launch(void* const* d_in, const int* in_sizes, int n_in,
                              void* d_out, int out_size) {
    const float* x = (const float*)d_in[0];   // [32, 64, 64, 512] fp32
    const float* W = (const float*)d_in[1];   // [512, 128] fp32
    float* out = (float*)d_out;               // [32, 128] fp32
    (void)in_sizes; (void)n_in; (void)out_size;

    const int smem_bytes = EDIM * EDIM * (int)sizeof(float);  // 64 KB (>= GEMM tiles)
    cudaFuncSetAttribute(weldon_gemm_pool_kernel,
                         cudaFuncAttributeMaxDynamicSharedMemorySize, smem_bytes);

    dim3 grid(NCHUNK, BATCH);
    weldon_gemm_pool_kernel<<<grid, 256, smem_bytes>>>(x, W);
    weldon_reduce_kernel<<<BATCH, EDIM>>>(out);
}

// round 3
// speedup vs baseline: 2.3808x; 2.3808x over previous
#include <cuda_runtime.h>
#include <cuda_bf16.h>
#include <cstdint>
#include <cfloat>

// ---------------- problem constants ----------------
#define BATCH     32
#define NSPATIAL  4096
#define CDIM      512
#define EDIM      128

#define TM        128                  // rows per CTA tile (M)
#define NCHUNK    (NSPATIAL / TM)      // 32 chunks per batch
#define KS        64                   // K per stage
#define NST       (CDIM / KS)          // 8 stages
#define ASTR      72                   // padded row stride (bf16 elems) = 144B
#define TILEB     (TM * ASTR * 2)      // 18432 B per tile buffer
#define SMEM_DYN  (8 * TILEB)          // Ah0 Ah1 Al0 Al1 Bh0 Bh1 Bl0 Bl1 = 144KB

// scratch: per (batch, chunk, e): top3 + min3 (6 floats) -> 3 MB
__device__ float g_cand[BATCH * NCHUNK * EDIM * 6];
// pre-converted W^T in bf16 hi/lo, plain [E=128][C=512] K-major
__device__ __align__(16) __nv_bfloat16 g_Wh[EDIM * CDIM];
__device__ __align__(16) __nv_bfloat16 g_Wl[EDIM * CDIM];

// ---------------- helpers ----------------
__device__ __forceinline__ uint32_t smem_u32(const void* p) {
    uint32_t a;
    asm("{ .reg .u64 t; cvta.to.shared.u64 t, %1; cvt.u32.u64 %0, t; }"
        : "=r"(a) : "l"(p));
    return a;
}
__device__ __forceinline__ void ldx4(uint32_t* r, uint32_t addr) {
    asm volatile("ldmatrix.sync.aligned.m8n8.x4.shared.b16 {%0,%1,%2,%3}, [%4];"
                 : "=r"(r[0]), "=r"(r[1]), "=r"(r[2]), "=r"(r[3]) : "r"(addr));
}
__device__ __forceinline__ void mma_bf16(float* c, const uint32_t* a,
                                         uint32_t b0, uint32_t b1) {
    asm volatile(
        "mma.sync.aligned.m16n8k16.row.col.f32.bf16.bf16.f32 "
        "{%0,%1,%2,%3}, {%4,%5,%6,%7}, {%8,%9}, {%0,%1,%2,%3};"
        : "+f"(c[0]), "+f"(c[1]), "+f"(c[2]), "+f"(c[3])
        : "r"(a[0]), "r"(a[1]), "r"(a[2]), "r"(a[3]), "r"(b0), "r"(b1));
}
__device__ __forceinline__ void cp16(uint32_t dst, const void* src) {
    asm volatile("cp.async.cg.shared.global [%0], [%1], 16;"
                 :: "r"(dst), "l"(src) : "memory");
}
#define CP_COMMIT() asm volatile("cp.async.commit_group;" ::: "memory")
#define CP_WAIT0()  asm volatile("cp.async.wait_group 0;" ::: "memory")

__device__ __forceinline__ void cvt_hilo(float x, float y, uint32_t& h, uint32_t& l) {
    __nv_bfloat162 hh = __float22bfloat162_rn(make_float2(x, y));
    float2 hf = __bfloat1622float2(hh);
    __nv_bfloat162 ll = __float22bfloat162_rn(make_float2(x - hf.x, y - hf.y));
    h = *(uint32_t*)&hh;
    l = *(uint32_t*)&ll;
}

// ---- sorted top-3 / min-3 insertion ----
__device__ __forceinline__ void ins_top(float v, float& t0, float& t1, float& t2) {
    if (v > t2) { if (v > t1) { t2 = t1; if (v > t0) { t1 = t0; t0 = v; } else t1 = v; } else t2 = v; }
}
__device__ __forceinline__ void ins_min(float v, float& m0, float& m1, float& m2) {
    if (v < m2) { if (v < m1) { m2 = m1; if (v < m0) { m1 = m0; m0 = v; } else m1 = v; } else m2 = v; }
}

// ================= kernel 0: W^T -> bf16 hi/lo =================
__global__ void weldon_prepw_kernel(const float* __restrict__ W) {
    int idx = blockIdx.x * 512 + threadIdx.x;   // 0..32767
    int e = idx >> 8;                           // 0..127
    int k = (idx & 255) * 2;                    // 0..510 step 2
    float w0 = W[(size_t)k * EDIM + e];
    float w1 = W[(size_t)(k + 1) * EDIM + e];
    uint32_t h, l;
    cvt_hilo(w0, w1, h, l);
    *(uint32_t*)&g_Wh[(size_t)e * CDIM + k] = h;
    *(uint32_t*)&g_Wl[(size_t)e * CDIM + k] = l;
}

// ================= kernel 1: HMMA GEMM + per-chunk pooling =================
// grid = (NCHUNK, BATCH), 512 threads (16 warps, 32x32 warp tiles)
__global__ __launch_bounds__(512, 1)
void weldon_gemm_pool_kernel(const float* __restrict__ x) {
    extern __shared__ char sm[];
    const uint32_t sb = smem_u32(sm);
    float* Fs = (float*)sm;                     // 64KB overlay after GEMM

    __shared__ float cand_s[4][EDIM][6];

    const int tid = threadIdx.x;
    const int lane = tid & 31;
    const int wid = tid >> 5;
    const int wm = wid & 3;                     // 4 M-groups of 32
    const int wn = wid >> 2;                    // 4 N-groups of 32
    const int chunk = blockIdx.x;
    const int b = blockIdx.y;

    const float* xg = x + ((size_t)b * NSPATIAL + (size_t)chunk * TM) * CDIM;

    // buffer byte offsets
    auto OFF_AH = [](int buf) { return buf * TILEB; };
    auto OFF_AL = [](int buf) { return 2 * TILEB + buf * TILEB; };
    auto OFF_BH = [](int buf) { return 4 * TILEB + buf * TILEB; };
    auto OFF_BL = [](int buf) { return 6 * TILEB + buf * TILEB; };

    // ldmatrix per-lane address offsets (bytes within a tile)
    int aoff[2], boff[2];
#pragma unroll
    for (int mt = 0; mt < 2; ++mt)
        aoff[mt] = ((wm * 32 + mt * 16 + (lane & 15)) * ASTR + (lane >> 4) * 8) * 2;
#pragma unroll
    for (int p = 0; p < 2; ++p)
        boff[p] = ((wn * 32 + p * 16 + (lane & 7) + (lane >> 4) * 8) * ASTR +
                   ((lane >> 3) & 1) * 8) * 2;

    float acc[2][4][4];
#pragma unroll
    for (int mt = 0; mt < 2; ++mt)
#pragma unroll
        for (int nt = 0; nt < 4; ++nt)
#pragma unroll
            for (int j = 0; j < 4; ++j) acc[mt][nt][j] = 0.f;

    // ---- A convert+store helper indices ----
    // A: 128 rows x 64 k fp32 = 2048 float4; 4 per thread
    // B: 128 rows x 64 bf16 = 1024 16B-chunks per (hi|lo); 2 per thread each

    // ---- prologue: stage 0 ----
    {
#pragma unroll
        for (int u = 0; u < 4; ++u) {
            int idx = tid + u * 512;
            int row = idx >> 4, kq = (idx & 15) * 4;
            float4 f = *(const float4*)(xg + (size_t)row * CDIM + kq);
            uint32_t h0, l0, h1, l1;
            cvt_hilo(f.x, f.y, h0, l0);
            cvt_hilo(f.z, f.w, h1, l1);
            int off = row * (ASTR * 2) + kq * 2;
            *(uint32_t*)(sm + OFF_AH(0) + off) = h0;
            *(uint32_t*)(sm + OFF_AH(0) + off + 4) = h1;
            *(uint32_t*)(sm + OFF_AL(0) + off) = l0;
            *(uint32_t*)(sm + OFF_AL(0) + off + 4) = l1;
        }
#pragma unroll
        for (int u = 0; u < 2; ++u) {
            int idx = tid + u * 512;
            int row = idx >> 3, ck = (idx & 7) * 8;
            int doff = row * (ASTR * 2) + ck * 2;
            cp16(sb + OFF_BH(0) + doff, (const char*)g_Wh + ((size_t)row * CDIM + ck) * 2);
            cp16(sb + OFF_BL(0) + doff, (const char*)g_Wl + ((size_t)row * CDIM + ck) * 2);
        }
        CP_COMMIT();
        CP_WAIT0();
        __syncthreads();
    }

    // ---- main stage loop ----
#pragma unroll
    for (int s = 0; s < NST; ++s) {
        const int buf = s & 1;
        const int nb = buf ^ 1;
        float4 pf[4];
        if (s + 1 < NST) {
            const int kb = (s + 1) * KS;
#pragma unroll
            for (int u = 0; u < 4; ++u) {
                int idx = tid + u * 512;
                int row = idx >> 4, kq = (idx & 15) * 4;
                pf[u] = *(const float4*)(xg + (size_t)row * CDIM + kb + kq);
            }
#pragma unroll
            for (int u = 0; u < 2; ++u) {
                int idx = tid + u * 512;
                int row = idx >> 3, ck = (idx & 7) * 8;
                int doff = row * (ASTR * 2) + ck * 2;
                cp16(sb + OFF_BH(nb) + doff,
                     (const char*)g_Wh + ((size_t)row * CDIM + kb + ck) * 2);
                cp16(sb + OFF_BL(nb) + doff,
                     (const char*)g_Wl + ((size_t)row * CDIM + kb + ck) * 2);
            }
            CP_COMMIT();
        }

        // ---- MMA over current buffer: 4 k16 steps ----
#pragma unroll
        for (int k16 = 0; k16 < 4; ++k16) {
            const int kbyte = k16 * 32;
            uint32_t a_h[2][4], a_l[2][4], b_h[2][4], b_l[2][4];
#pragma unroll
            for (int mt = 0; mt < 2; ++mt) {
                ldx4(a_h[mt], sb + OFF_AH(buf) + aoff[mt] + kbyte);
                ldx4(a_l[mt], sb + OFF_AL(buf) + aoff[mt] + kbyte);
            }
#pragma unroll
            for (int p = 0; p < 2; ++p) {
                ldx4(b_h[p], sb + OFF_BH(buf) + boff[p] + kbyte);
                ldx4(b_l[p], sb + OFF_BL(buf) + boff[p] + kbyte);
            }
#pragma unroll
            for (int mt = 0; mt < 2; ++mt)
#pragma unroll
                for (int nt = 0; nt < 4; ++nt) {
                    uint32_t bh0 = b_h[nt >> 1][(nt & 1) * 2];
                    uint32_t bh1 = b_h[nt >> 1][(nt & 1) * 2 + 1];
                    uint32_t bl0 = b_l[nt >> 1][(nt & 1) * 2];
                    uint32_t bl1 = b_l[nt >> 1][(nt & 1) * 2 + 1];
                    mma_bf16(acc[mt][nt], a_h[mt], bh0, bh1);
                    mma_bf16(acc[mt][nt], a_l[mt], bh0, bh1);
                    mma_bf16(acc[mt][nt], a_h[mt], bl0, bl1);
                }
        }

        if (s + 1 < NST) {
#pragma unroll
            for (int u = 0; u < 4; ++u) {
                int idx = tid + u * 512;
                int row = idx >> 4, kq = (idx & 15) * 4;
                uint32_t h0, l0, h1, l1;
                cvt_hilo(pf[u].x, pf[u].y, h0, l0);
                cvt_hilo(pf[u].z, pf[u].w, h1, l1);
                int off = row * (ASTR * 2) + kq * 2;
                *(uint32_t*)(sm + OFF_AH(nb) + off) = h0;
                *(uint32_t*)(sm + OFF_AH(nb) + off + 4) = h1;
                *(uint32_t*)(sm + OFF_AL(nb) + off) = l0;
                *(uint32_t*)(sm + OFF_AL(nb) + off + 4) = l1;
            }
            CP_WAIT0();
        }
        __syncthreads();
    }

    // ---- epilogue: acc -> Fs (overlay), then per-column pooling ----
    {
        const int gid = lane >> 2, tig = lane & 3;
#pragma unroll
        for (int mt = 0; mt < 2; ++mt)
#pragma unroll
            for (int nt = 0; nt < 4; ++nt) {
                int m0 = wm * 32 + mt * 16 + gid;
                int n0 = wn * 32 + nt * 8 + tig * 2;
                Fs[m0 * EDIM + n0] = acc[mt][nt][0];
                Fs[m0 * EDIM + n0 + 1] = acc[mt][nt][1];
                Fs[(m0 + 8) * EDIM + n0] = acc[mt][nt][2];
                Fs[(m0 + 8) * EDIM + n0 + 1] = acc[mt][nt][3];
            }
    }
    __syncthreads();

    {
        const int sub = tid >> 7;       // 0..3, each handles 32 rows
        const int e = tid & 127;
        float t0 = -FLT_MAX, t1 = -FLT_MAX, t2 = -FLT_MAX;
        float m0 = FLT_MAX, m1 = FLT_MAX, m2 = FLT_MAX;
#pragma unroll 4
        for (int r = sub * 32; r < sub * 32 + 32; ++r) {
            float v = Fs[r * EDIM + e];
            ins_top(v, t0, t1, t2);
            ins_min(v, m0, m1, m2);
        }
        cand_s[sub][e][0] = t0; cand_s[sub][e][1] = t1; cand_s[sub][e][2] = t2;
        cand_s[sub][e][3] = m0; cand_s[sub][e][4] = m1; cand_s[sub][e][5] = m2;
    }
    __syncthreads();

    if (tid < EDIM) {
        float t0 = -FLT_MAX, t1 = -FLT_MAX, t2 = -FLT_MAX;
        float m0 = FLT_MAX, m1 = FLT_MAX, m2 = FLT_MAX;
#pragma unroll
        for (int s2 = 0; s2 < 4; ++s2) {
            ins_top(cand_s[s2][tid][0], t0, t1, t2);
            ins_top(cand_s[s2][tid][1], t0, t1, t2);
            ins_top(cand_s[s2][tid][2], t0, t1, t2);
            ins_min(cand_s[s2][tid][3], m0, m1, m2);
            ins_min(cand_s[s2][tid][4], m0, m1, m2);
            ins_min(cand_s[s2][tid][5], m0, m1, m2);
        }
        float* dst = g_cand + ((size_t)(b * NCHUNK + chunk) * EDIM + tid) * 6;
        dst[0] = t0; dst[1] = t1; dst[2] = t2;
        dst[3] = m0; dst[4] = m1; dst[5] = m2;
    }
}

// ================= kernel 2: merge + pool + L2 normalize =================
// grid = BATCH, block = (128, 8)
__global__ void weldon_reduce_kernel(float* __restrict__ out) {
    const int b = blockIdx.x;
    const int e = threadIdx.x;
    const int sub = threadIdx.y;

    __shared__ float cand_s[8][EDIM][6];
    __shared__ float ps_s[EDIM];
    __shared__ float wsum[4];

    float t0 = -FLT_MAX, t1 = -FLT_MAX, t2 = -FLT_MAX;
    float m0 = FLT_MAX, m1 = FLT_MAX, m2 = FLT_MAX;
    const float* bb = g_cand + (size_t)b * NCHUNK * EDIM * 6 + (size_t)e * 6;
#pragma unroll
    for (int c = sub; c < NCHUNK; c += 8) {
        const float* p = bb + (size_t)c * EDIM * 6;
        ins_top(p[0], t0, t1, t2);
        ins_top(p[1], t0, t1, t2);
        ins_top(p[2], t0, t1, t2);
        ins_min(p[3], m0, m1, m2);
        ins_min(p[4], m0, m1, m2);
        ins_min(p[5], m0, m1, m2);
    }
    cand_s[sub][e][0] = t0; cand_s[sub][e][1] = t1; cand_s[sub][e][2] = t2;
    cand_s[sub][e][3] = m0; cand_s[sub][e][4] = m1; cand_s[sub][e][5] = m2;
    __syncthreads();

    if (sub == 0) {
        for (int s2 = 1; s2 < 8; ++s2) {
            ins_top(cand_s[s2][e][0], t0, t1, t2);
            ins_top(cand_s[s2][e][1], t0, t1, t2);
            ins_top(cand_s[s2][e][2], t0, t1, t2);
            ins_min(cand_s[s2][e][3], m0, m1, m2);
            ins_min(cand_s[s2][e][4], m0, m1, m2);
            ins_min(cand_s[s2][e][5], m0, m1, m2);
        }
        float ps = (t0 + t1 + t2) + (m0 + m1 + m2);
        ps_s[e] = ps;
        float sq = ps * ps;
#pragma unroll
        for (int off = 16; off > 0; off >>= 1)
            sq += __shfl_xor_sync(0xffffffffu, sq, off);
        if ((e & 31) == 0) wsum[e >> 5] = sq;
    }
    __syncthreads();
    if (sub == 0) {
        float tot = wsum[0] + wsum[1] + wsum[2] + wsum[3];
        out[b * EDIM + e] = ps_s[e] * rsqrtf(fmaxf(tot, 1e-12f));
    }
}

extern "C" void kernel_launch(void* const* d_in, const int* in_sizes, int n_in,
                              void* d_out, int out_size) {
    const float* x = (const float*)d_in[0];   // [32, 64, 64, 512] fp32
    const float* W = (const float*)d_in[1];   // [512, 128] fp32
    float* out = (float*)d_out;               // [32, 128] fp32
    (void)in_sizes; (void)n_in; (void)out_size;

    cudaFuncSetAttribute(weldon_gemm_pool_kernel,
                         cudaFuncAttributeMaxDynamicSharedMemorySize, SMEM_DYN);

    weldon_prepw_kernel<<<64, 512>>>(W);
    weldon_gemm_pool_kernel<<<dim3(NCHUNK, BATCH), 512, SMEM_DYN>>>(x);
    weldon_reduce_kernel<<<BATCH, dim3(EDIM, 8)>>>(out);
}

// round 4
// speedup vs baseline: 2.7925x; 1.1729x over previous
#include <cuda_runtime.h>
#include <cuda_fp16.h>
#include <cstdint>
#include <cfloat>

// ---------------- problem constants ----------------
#define BATCH     32
#define NSPATIAL  4096
#define CDIM      512
#define EDIM      128

#define TM        128                  // rows per CTA tile (M)
#define NCHUNK    (NSPATIAL / TM)      // 32 chunks per batch
#define KS        64                   // K per stage
#define NST       (CDIM / KS)          // 8 stages
#define ASTR      72                   // padded row stride (fp16 elems) = 144B
#define TILEB     (TM * ASTR * 2)      // 18432 B per tile buffer
#define SMEM_DYN  (6 * TILEB)          // Ah0 Ah1 Bh0 Bh1 Bl0 Bl1 = 110.6KB

// scratch: per (batch, chunk, e): top3 + min3 (6 floats) -> 3 MB
__device__ float g_cand[BATCH * NCHUNK * EDIM * 6];
// pre-converted W^T in fp16 hi/lo, plain [E=128][C=512] K-major
__device__ __align__(16) __half g_Wh[EDIM * CDIM];
__device__ __align__(16) __half g_Wl[EDIM * CDIM];

// ---------------- helpers ----------------
__device__ __forceinline__ uint32_t smem_u32(const void* p) {
    uint32_t a;
    asm("{ .reg .u64 t; cvta.to.shared.u64 t, %1; cvt.u32.u64 %0, t; }"
        : "=r"(a) : "l"(p));
    return a;
}
__device__ __forceinline__ void ldx4(uint32_t* r, uint32_t addr) {
    asm volatile("ldmatrix.sync.aligned.m8n8.x4.shared.b16 {%0,%1,%2,%3}, [%4];"
                 : "=r"(r[0]), "=r"(r[1]), "=r"(r[2]), "=r"(r[3]) : "r"(addr));
}
__device__ __forceinline__ void mma_f16(float* c, const uint32_t* a,
                                        uint32_t b0, uint32_t b1) {
    asm volatile(
        "mma.sync.aligned.m16n8k16.row.col.f32.f16.f16.f32 "
        "{%0,%1,%2,%3}, {%4,%5,%6,%7}, {%8,%9}, {%0,%1,%2,%3};"
        : "+f"(c[0]), "+f"(c[1]), "+f"(c[2]), "+f"(c[3])
        : "r"(a[0]), "r"(a[1]), "r"(a[2]), "r"(a[3]), "r"(b0), "r"(b1));
}
__device__ __forceinline__ void cp16(uint32_t dst, const void* src) {
    asm volatile("cp.async.cg.shared.global [%0], [%1], 16;"
                 :: "r"(dst), "l"(src) : "memory");
}
#define CP_COMMIT() asm volatile("cp.async.commit_group;" ::: "memory")
#define CP_WAIT0()  asm volatile("cp.async.wait_group 0;" ::: "memory")

// fp32 pair -> fp16x2 (single rounding)
__device__ __forceinline__ uint32_t cvt_h2(float x, float y) {
    __half2 h = __floats2half2_rn(x, y);
    return *(uint32_t*)&h;
}
// fp32 pair -> fp16 hi + fp16 lo (residual)
__device__ __forceinline__ void cvt_hilo(float x, float y, uint32_t& h, uint32_t& l) {
    __half2 hh = __floats2half2_rn(x, y);
    float2 hf = __half22float2(hh);
    __half2 ll = __floats2half2_rn(x - hf.x, y - hf.y);
    h = *(uint32_t*)&hh;
    l = *(uint32_t*)&ll;
}

// ---- sorted top-3 / min-3 insertion ----
__device__ __forceinline__ void ins_top(float v, float& t0, float& t1, float& t2) {
    if (v > t2) { if (v > t1) { t2 = t1; if (v > t0) { t1 = t0; t0 = v; } else t1 = v; } else t2 = v; }
}
__device__ __forceinline__ void ins_min(float v, float& m0, float& m1, float& m2) {
    if (v < m2) { if (v < m1) { m2 = m1; if (v < m0) { m1 = m0; m0 = v; } else m1 = v; } else m2 = v; }
}

// ================= kernel 0: W^T -> fp16 hi/lo =================
__global__ void weldon_prepw_kernel(const float* __restrict__ W) {
    int idx = blockIdx.x * 512 + threadIdx.x;   // 0..32767
    int e = idx >> 8;                           // 0..127
    int k = (idx & 255) * 2;                    // 0..510 step 2
    float w0 = W[(size_t)k * EDIM + e];
    float w1 = W[(size_t)(k + 1) * EDIM + e];
    uint32_t h, l;
    cvt_hilo(w0, w1, h, l);
    *(uint32_t*)&g_Wh[(size_t)e * CDIM + k] = h;
    *(uint32_t*)&g_Wl[(size_t)e * CDIM + k] = l;
}

// ================= kernel 1: HMMA GEMM + per-chunk pooling =================
// grid = (NCHUNK, BATCH), 512 threads (16 warps, 32x32 warp tiles)
__global__ __launch_bounds__(512, 1)
void weldon_gemm_pool_kernel(const float* __restrict__ x) {
    extern __shared__ char sm[];
    const uint32_t sb = smem_u32(sm);
    float* Fs = (float*)sm;                     // 64KB overlay after GEMM

    __shared__ float cand_s[4][EDIM][6];

    const int tid = threadIdx.x;
    const int lane = tid & 31;
    const int wid = tid >> 5;
    const int wm = wid & 3;                     // 4 M-groups of 32
    const int wn = wid >> 2;                    // 4 N-groups of 32
    const int chunk = blockIdx.x;
    const int b = blockIdx.y;

    const float* xg = x + ((size_t)b * NSPATIAL + (size_t)chunk * TM) * CDIM;

    // buffer byte offsets: A hi (2 bufs), B hi (2), B lo (2)
    auto OFF_A  = [](int buf) { return buf * TILEB; };
    auto OFF_BH = [](int buf) { return (2 + buf) * TILEB; };
    auto OFF_BL = [](int buf) { return (4 + buf) * TILEB; };

    // ldmatrix per-lane address offsets (bytes within a tile)
    int aoff[2], boff[2];
#pragma unroll
    for (int mt = 0; mt < 2; ++mt)
        aoff[mt] = ((wm * 32 + mt * 16 + (lane & 15)) * ASTR + (lane >> 4) * 8) * 2;
#pragma unroll
    for (int p = 0; p < 2; ++p)
        boff[p] = ((wn * 32 + p * 16 + (lane & 7) + (lane >> 4) * 8) * ASTR +
                   ((lane >> 3) & 1) * 8) * 2;

    float acc[2][4][4];
#pragma unroll
    for (int mt = 0; mt < 2; ++mt)
#pragma unroll
        for (int nt = 0; nt < 4; ++nt)
#pragma unroll
            for (int j = 0; j < 4; ++j) acc[mt][nt][j] = 0.f;

    // ---- prologue: stage 0 ----
    {
#pragma unroll
        for (int u = 0; u < 4; ++u) {
            int idx = tid + u * 512;            // 0..2047 float4s
            int row = idx >> 4, kq = (idx & 15) * 4;
            float4 f = *(const float4*)(xg + (size_t)row * CDIM + kq);
            uint2 hv = make_uint2(cvt_h2(f.x, f.y), cvt_h2(f.z, f.w));
            *(uint2*)(sm + OFF_A(0) + row * (ASTR * 2) + kq * 2) = hv;
        }
#pragma unroll
        for (int u = 0; u < 2; ++u) {
            int idx = tid + u * 512;            // 0..1023 16B chunks
            int row = idx >> 3, ck = (idx & 7) * 8;
            int doff = row * (ASTR * 2) + ck * 2;
            cp16(sb + OFF_BH(0) + doff, (const char*)g_Wh + ((size_t)row * CDIM + ck) * 2);
            cp16(sb + OFF_BL(0) + doff, (const char*)g_Wl + ((size_t)row * CDIM + ck) * 2);
        }
        CP_COMMIT();
        CP_WAIT0();
        __syncthreads();
    }

    // ---- main stage loop ----
#pragma unroll
    for (int s = 0; s < NST; ++s) {
        const int buf = s & 1;
        const int nb = buf ^ 1;
        float4 pf[4];
        if (s + 1 < NST) {
            const int kb = (s + 1) * KS;
#pragma unroll
            for (int u = 0; u < 4; ++u) {
                int idx = tid + u * 512;
                int row = idx >> 4, kq = (idx & 15) * 4;
                pf[u] = *(const float4*)(xg + (size_t)row * CDIM + kb + kq);
            }
#pragma unroll
            for (int u = 0; u < 2; ++u) {
                int idx = tid + u * 512;
                int row = idx >> 3, ck = (idx & 7) * 8;
                int doff = row * (ASTR * 2) + ck * 2;
                cp16(sb + OFF_BH(nb) + doff,
                     (const char*)g_Wh + ((size_t)row * CDIM + kb + ck) * 2);
                cp16(sb + OFF_BL(nb) + doff,
                     (const char*)g_Wl + ((size_t)row * CDIM + kb + ck) * 2);
            }
            CP_COMMIT();
        }

        // ---- MMA over current buffer: 4 k16 steps, 2 products ----
#pragma unroll
        for (int k16 = 0; k16 < 4; ++k16) {
            const int kbyte = k16 * 32;
            uint32_t a_r[2][4], b_h[2][4], b_l[2][4];
#pragma unroll
            for (int mt = 0; mt < 2; ++mt)
                ldx4(a_r[mt], sb + OFF_A(buf) + aoff[mt] + kbyte);
#pragma unroll
            for (int p = 0; p < 2; ++p) {
                ldx4(b_h[p], sb + OFF_BH(buf) + boff[p] + kbyte);
                ldx4(b_l[p], sb + OFF_BL(buf) + boff[p] + kbyte);
            }
#pragma unroll
            for (int mt = 0; mt < 2; ++mt)
#pragma unroll
                for (int nt = 0; nt < 4; ++nt) {
                    uint32_t bh0 = b_h[nt >> 1][(nt & 1) * 2];
                    uint32_t bh1 = b_h[nt >> 1][(nt & 1) * 2 + 1];
                    uint32_t bl0 = b_l[nt >> 1][(nt & 1) * 2];
                    uint32_t bl1 = b_l[nt >> 1][(nt & 1) * 2 + 1];
                    mma_f16(acc[mt][nt], a_r[mt], bh0, bh1);
                    mma_f16(acc[mt][nt], a_r[mt], bl0, bl1);
                }
        }

        if (s + 1 < NST) {
#pragma unroll
            for (int u = 0; u < 4; ++u) {
                int idx = tid + u * 512;
                int row = idx >> 4, kq = (idx & 15) * 4;
                uint2 hv = make_uint2(cvt_h2(pf[u].x, pf[u].y), cvt_h2(pf[u].z, pf[u].w));
                *(uint2*)(sm + OFF_A(nb) + row * (ASTR * 2) + kq * 2) = hv;
            }
            CP_WAIT0();
        }
        __syncthreads();
    }

    // ---- epilogue: acc -> Fs (overlay), then per-column pooling ----
    {
        const int gid = lane >> 2, tig = lane & 3;
#pragma unroll
        for (int mt = 0; mt < 2; ++mt)
#pragma unroll
            for (int nt = 0; nt < 4; ++nt) {
                int m0 = wm * 32 + mt * 16 + gid;
                int n0 = wn * 32 + nt * 8 + tig * 2;
                Fs[m0 * EDIM + n0] = acc[mt][nt][0];
                Fs[m0 * EDIM + n0 + 1] = acc[mt][nt][1];
                Fs[(m0 + 8) * EDIM + n0] = acc[mt][nt][2];
                Fs[(m0 + 8) * EDIM + n0 + 1] = acc[mt][nt][3];
            }
    }
    __syncthreads();

    {
        const int sub = tid >> 7;       // 0..3, each handles 32 rows
        const int e = tid & 127;
        float t0 = -FLT_MAX, t1 = -FLT_MAX, t2 = -FLT_MAX;
        float m0 = FLT_MAX, m1 = FLT_MAX, m2 = FLT_MAX;
#pragma unroll 4
        for (int r = sub * 32; r < sub * 32 + 32; ++r) {
            float v = Fs[r * EDIM + e];
            ins_top(v, t0, t1, t2);
            ins_min(v, m0, m1, m2);
        }
        cand_s[sub][e][0] = t0; cand_s[sub][e][1] = t1; cand_s[sub][e][2] = t2;
        cand_s[sub][e][3] = m0; cand_s[sub][e][4] = m1; cand_s[sub][e][5] = m2;
    }
    __syncthreads();

    if (tid < EDIM) {
        float t0 = -FLT_MAX, t1 = -FLT_MAX, t2 = -FLT_MAX;
        float m0 = FLT_MAX, m1 = FLT_MAX, m2 = FLT_MAX;
#pragma unroll
        for (int s2 = 0; s2 < 4; ++s2) {
            ins_top(cand_s[s2][tid][0], t0, t1, t2);
            ins_top(cand_s[s2][tid][1], t0, t1, t2);
            ins_top(cand_s[s2][tid][2], t0, t1, t2);
            ins_min(cand_s[s2][tid][3], m0, m1, m2);
            ins_min(cand_s[s2][tid][4], m0, m1, m2);
            ins_min(cand_s[s2][tid][5], m0, m1, m2);
        }
        float* dst = g_cand + ((size_t)(b * NCHUNK + chunk) * EDIM + tid) * 6;
        dst[0] = t0; dst[1] = t1; dst[2] = t2;
        dst[3] = m0; dst[4] = m1; dst[5] = m2;
    }
}

// ================= kernel 2: merge + pool + L2 normalize =================
// grid = BATCH, block = (128, 8)
__global__ void weldon_reduce_kernel(float* __restrict__ out) {
    const int b = blockIdx.x;
    const int e = threadIdx.x;
    const int sub = threadIdx.y;

    __shared__ float cand_s[8][EDIM][6];
    __shared__ float ps_s[EDIM];
    __shared__ float wsum[4];

    float t0 = -FLT_MAX, t1 = -FLT_MAX, t2 = -FLT_MAX;
    float m0 = FLT_MAX, m1 = FLT_MAX, m2 = FLT_MAX;
    const float* bb = g_cand + (size_t)b * NCHUNK * EDIM * 6 + (size_t)e * 6;
#pragma unroll
    for (int c = sub; c < NCHUNK; c += 8) {
        const float* p = bb + (size_t)c * EDIM * 6;
        ins_top(p[0], t0, t1, t2);
        ins_top(p[1], t0, t1, t2);
        ins_top(p[2], t0, t1, t2);
        ins_min(p[3], m0, m1, m2);
        ins_min(p[4], m0, m1, m2);
        ins_min(p[5], m0, m1, m2);
    }
    cand_s[sub][e][0] = t0; cand_s[sub][e][1] = t1; cand_s[sub][e][2] = t2;
    cand_s[sub][e][3] = m0; cand_s[sub][e][4] = m1; cand_s[sub][e][5] = m2;
    __syncthreads();

    if (sub == 0) {
        for (int s2 = 1; s2 < 8; ++s2) {
            ins_top(cand_s[s2][e][0], t0, t1, t2);
            ins_top(cand_s[s2][e][1], t0, t1, t2);
            ins_top(cand_s[s2][e][2], t0, t1, t2);
            ins_min(cand_s[s2][e][3], m0, m1, m2);
            ins_min(cand_s[s2][e][4], m0, m1, m2);
            ins_min(cand_s[s2][e][5], m0, m1, m2);
        }
        float ps = (t0 + t1 + t2) + (m0 + m1 + m2);
        ps_s[e] = ps;
        float sq = ps * ps;
#pragma unroll
        for (int off = 16; off > 0; off >>= 1)
            sq += __shfl_xor_sync(0xffffffffu, sq, off);
        if ((e & 31) == 0) wsum[e >> 5] = sq;
    }
    __syncthreads();
    if (sub == 0) {
        float tot = wsum[0] + wsum[1] + wsum[2] + wsum[3];
        out[b * EDIM + e] = ps_s[e] * rsqrtf(fmaxf(tot, 1e-12f));
    }
}

extern "C" void kernel_launch(void* const* d_in, const int* in_sizes, int n_in,
                              void* d_out, int out_size) {
    const float* x = (const float*)d_in[0];   // [32, 64, 64, 512] fp32
    const float* W = (const float*)d_in[1];   // [512, 128] fp32
    float* out = (float*)d_out;               // [32, 128] fp32
    (void)in_sizes; (void)n_in; (void)out_size;

    cudaFuncSetAttribute(weldon_gemm_pool_kernel,
                         cudaFuncAttributeMaxDynamicSharedMemorySize, SMEM_DYN);

    weldon_prepw_kernel<<<64, 512>>>(W);
    weldon_gemm_pool_kernel<<<dim3(NCHUNK, BATCH), 512, SMEM_DYN>>>(x);
    weldon_reduce_kernel<<<BATCH, dim3(EDIM, 8)>>>(out);
}